// round 1
// baseline (speedup 1.0000x reference)
#include <cuda_runtime.h>

#define N_NODES_C  500000
#define N_EDGES_C  8000000
#define N_GRAPHS_C 1000

// Scratch (no cudaMalloc allowed)
__device__ float d_eon[N_NODES_C];        // segment_sum of edge outputs per receiver
__device__ float d_g[N_GRAPHS_C * 11];    // per-graph accumulators
__device__ float d_EW[96];                // folded edge-stage weights

__device__ __forceinline__ float selu_f(float x) {
    const float alpha = 1.6732632423543772f;
    const float scale = 1.0507009873554805f;
    float ex = __expf(x);
    return x > 0.0f ? scale * x : scale * alpha * (ex - 1.0f);
}

// ---------------------------------------------------------------------------
// Setup: fold pn_w2 into ue_w1[1:,:]:  M = pn_w2 @ ue_w1[1:,:],  d = pn_b2 @ ue_w1[1:,:] + ue_b1
// Layout of d_EW:
//   [0:20)  pn_w1 (2x10)     [20:30) pn_b1
//   [30:80) M (10x5)         [80:85) d
//   [85:90) ue_w1 row 0      [90:95) ue_w2      [95] ue_b2
// ---------------------------------------------------------------------------
__global__ void setup_kernel(const float* __restrict__ pn_w1, const float* __restrict__ pn_b1,
                             const float* __restrict__ pn_w2, const float* __restrict__ pn_b2,
                             const float* __restrict__ ue_w1, const float* __restrict__ ue_b1,
                             const float* __restrict__ ue_w2, const float* __restrict__ ue_b2) {
    int t = threadIdx.x;
    if (t < 20) d_EW[t] = pn_w1[t];
    if (t < 10) d_EW[20 + t] = pn_b1[t];
    if (t < 50) {
        int j = t / 5, k = t % 5;
        float m = 0.0f;
        for (int q = 0; q < 10; ++q)
            m += pn_w2[j * 10 + q] * ue_w1[(1 + q) * 5 + k];
        d_EW[30 + t] = m;
    }
    if (t < 5) {
        float dd = ue_b1[t];
        for (int q = 0; q < 10; ++q)
            dd += pn_b2[q] * ue_w1[(1 + q) * 5 + t];
        d_EW[80 + t] = dd;
        d_EW[85 + t] = ue_w1[t];   // ue_w1[0][k]
        d_EW[90 + t] = ue_w2[t];
    }
    if (t == 0) d_EW[95] = ue_b2[0];
}

// ---------------------------------------------------------------------------
// Edge stage: per edge, pn hidden + folded c, then 3 scalar ue iterations.
// 96 weights register-resident, amortized over ~100 edges/thread.
// ---------------------------------------------------------------------------
__global__ __launch_bounds__(256) void edge_kernel(
        const float* __restrict__ nodes, const float* __restrict__ edges,
        const int* __restrict__ senders, const int* __restrict__ receivers) {
    float W[96];
#pragma unroll
    for (int i = 0; i < 96; ++i) W[i] = d_EW[i];

    int stride = gridDim.x * blockDim.x;
    for (int e = blockIdx.x * blockDim.x + threadIdx.x; e < N_EDGES_C; e += stride) {
        int r = receivers[e];
        int s = senders[e];
        float nr = __ldg(nodes + r);
        float ns = __ldg(nodes + s);

        float c0 = W[80], c1 = W[81], c2 = W[82], c3 = W[83], c4 = W[84];
#pragma unroll
        for (int j = 0; j < 10; ++j) {
            float h = selu_f(fmaf(nr, W[j], fmaf(ns, W[10 + j], W[20 + j])));
            c0 = fmaf(h, W[30 + j * 5 + 0], c0);
            c1 = fmaf(h, W[30 + j * 5 + 1], c1);
            c2 = fmaf(h, W[30 + j * 5 + 2], c2);
            c3 = fmaf(h, W[30 + j * 5 + 3], c3);
            c4 = fmaf(h, W[30 + j * 5 + 4], c4);
        }
        float ev = edges[e];
#pragma unroll
        for (int it = 0; it < 3; ++it) {
            float acc = W[95];
            acc = fmaf(selu_f(fmaf(ev, W[85], c0)), W[90], acc);
            acc = fmaf(selu_f(fmaf(ev, W[86], c1)), W[91], acc);
            acc = fmaf(selu_f(fmaf(ev, W[87], c2)), W[92], acc);
            acc = fmaf(selu_f(fmaf(ev, W[88], c3)), W[93], acc);
            acc = fmaf(selu_f(fmaf(ev, W[89], c4)), W[94], acc);
            ev = acc;
        }
        atomicAdd(&d_eon[r], ev);
    }
}

// ---------------------------------------------------------------------------
// Node stage: pe MLP + 3 un iterations, warp-aggregated segment sum into d_g
// (graph_ids sorted, ~500 nodes/graph -> almost all warps uniform).
// N_NODES % 32 == 0 and stride % 32 == 0 => warp-uniform loop bounds.
// ---------------------------------------------------------------------------
__global__ __launch_bounds__(256) void node_kernel(
        const float* __restrict__ nodes, const int* __restrict__ graph_ids,
        const float* __restrict__ pe_w1, const float* __restrict__ pe_b1,
        const float* __restrict__ pe_w2, const float* __restrict__ pe_b2,
        const float* __restrict__ un_w1, const float* __restrict__ un_b1,
        const float* __restrict__ un_w2, const float* __restrict__ un_b2) {
    float PW1[5], PB1[5], PW2[50], PB2[10];
    float UW1[55], UB1[5], UW2[5], UB2v;
#pragma unroll
    for (int i = 0; i < 5; ++i) {
        PW1[i] = __ldg(pe_w1 + i); PB1[i] = __ldg(pe_b1 + i);
        UB1[i] = __ldg(un_b1 + i); UW2[i] = __ldg(un_w2 + i);
    }
#pragma unroll
    for (int i = 0; i < 50; ++i) PW2[i] = __ldg(pe_w2 + i);
#pragma unroll
    for (int i = 0; i < 10; ++i) PB2[i] = __ldg(pe_b2 + i);
#pragma unroll
    for (int i = 0; i < 55; ++i) UW1[i] = __ldg(un_w1 + i);
    UB2v = __ldg(un_b2);

    int stride = gridDim.x * blockDim.x;
    for (int n = blockIdx.x * blockDim.x + threadIdx.x; n < N_NODES_C; n += stride) {
        float eon = d_eon[n];
        float v[11];
        float hid[5];
#pragma unroll
        for (int k = 0; k < 5; ++k) hid[k] = selu_f(fmaf(eon, PW1[k], PB1[k]));
#pragma unroll
        for (int j = 0; j < 10; ++j) {
            float acc = PB2[j];
#pragma unroll
            for (int k = 0; k < 5; ++k) acc = fmaf(hid[k], PW2[k * 10 + j], acc);
            v[1 + j] = acc;                         // h2_edges[j]
        }
        float c[5];
#pragma unroll
        for (int k = 0; k < 5; ++k) {
            float acc = UB1[k];
#pragma unroll
            for (int t = 0; t < 10; ++t) acc = fmaf(v[1 + t], UW1[(1 + t) * 5 + k], acc);
            c[k] = acc;
        }
        float x = nodes[n];
#pragma unroll
        for (int it = 0; it < 3; ++it) {
            float acc = UB2v;
#pragma unroll
            for (int k = 0; k < 5; ++k)
                acc = fmaf(selu_f(fmaf(x, UW1[k], c[k])), UW2[k], acc);
            x = acc;
        }
        v[0] = x;                                   // h2_nodes

        int gid = graph_ids[n];
        const unsigned mask = 0xffffffffu;
        int g0 = __shfl_sync(mask, gid, 0);
        bool uni = __all_sync(mask, gid == g0);
        if (uni) {
#pragma unroll
            for (int j = 0; j < 11; ++j) {
                float vv = v[j];
#pragma unroll
                for (int off = 16; off > 0; off >>= 1)
                    vv += __shfl_down_sync(mask, vv, off);
                if ((threadIdx.x & 31) == 0) atomicAdd(&d_g[g0 * 11 + j], vv);
            }
        } else {
#pragma unroll
            for (int j = 0; j < 11; ++j)
                atomicAdd(&d_g[gid * 11 + j], v[j]);
        }
    }
}

// ---------------------------------------------------------------------------
// Final: pr MLP + softmax per graph (trivial: 1000 rows)
// ---------------------------------------------------------------------------
__global__ void graph_kernel(const float* __restrict__ pr_w1, const float* __restrict__ pr_b1,
                             const float* __restrict__ pr_w2, const float* __restrict__ pr_b2,
                             float* __restrict__ out) {
    int g = blockIdx.x * blockDim.x + threadIdx.x;
    if (g >= N_GRAPHS_C) return;
    float gv[11];
#pragma unroll
    for (int i = 0; i < 11; ++i) gv[i] = d_g[g * 11 + i];
    float hid[10];
#pragma unroll
    for (int j = 0; j < 10; ++j) {
        float acc = __ldg(pr_b1 + j);
#pragma unroll
        for (int i = 0; i < 11; ++i) acc = fmaf(gv[i], __ldg(pr_w1 + i * 10 + j), acc);
        hid[j] = selu_f(acc);
    }
    float o[10];
    float mx = -1e30f;
#pragma unroll
    for (int k = 0; k < 10; ++k) {
        float acc = __ldg(pr_b2 + k);
#pragma unroll
        for (int j = 0; j < 10; ++j) acc = fmaf(hid[j], __ldg(pr_w2 + j * 10 + k), acc);
        o[k] = acc;
        mx = fmaxf(mx, acc);
    }
    float sum = 0.0f;
#pragma unroll
    for (int k = 0; k < 10; ++k) { o[k] = __expf(o[k] - mx); sum += o[k]; }
    float inv = 1.0f / sum;
#pragma unroll
    for (int k = 0; k < 10; ++k) out[g * 10 + k] = o[k] * inv;
}

// ---------------------------------------------------------------------------
extern "C" void kernel_launch(void* const* d_in, const int* in_sizes, int n_in,
                              void* d_out, int out_size) {
    const float* nodes = (const float*)d_in[0];
    const float* edges = (const float*)d_in[1];
    const int *senders, *receivers, *graph_ids;
    const float* w[20];

    if (in_sizes[2] == N_EDGES_C) {
        // setup_inputs() dict order: nodes, edges, senders, receivers, graph_ids, [num_graphs], weights...
        senders   = (const int*)d_in[2];
        receivers = (const int*)d_in[3];
        graph_ids = (const int*)d_in[4];
        int base = (n_in > 25 && in_sizes[5] == 1) ? 6 : 5;
        for (int i = 0; i < 20; ++i) w[i] = (const float*)d_in[base + i];
    } else {
        // reference() signature order: nodes, edges, weights..., senders, receivers, graph_ids, [num_graphs]
        for (int i = 0; i < 20; ++i) w[i] = (const float*)d_in[2 + i];
        senders   = (const int*)d_in[22];
        receivers = (const int*)d_in[23];
        graph_ids = (const int*)d_in[24];
    }

    void* eon_ptr = nullptr;
    void* g_ptr   = nullptr;
    cudaGetSymbolAddress(&eon_ptr, d_eon);
    cudaGetSymbolAddress(&g_ptr, d_g);
    cudaMemsetAsync(eon_ptr, 0, N_NODES_C * sizeof(float));
    cudaMemsetAsync(g_ptr,   0, N_GRAPHS_C * 11 * sizeof(float));

    setup_kernel<<<1, 64>>>(w[0], w[1], w[2], w[3], w[4], w[5], w[6], w[7]);
    edge_kernel<<<296, 256>>>(nodes, edges, senders, receivers);
    node_kernel<<<148, 256>>>(nodes, graph_ids,
                              w[8], w[9], w[10], w[11],
                              w[12], w[13], w[14], w[15]);
    graph_kernel<<<8, 128>>>(w[16], w[17], w[18], w[19], (float*)d_out);
}

// round 2
// speedup vs baseline: 1.0696x; 1.0696x over previous
#include <cuda_runtime.h>

#define N_NODES_C  500000
#define N_EDGES_C  8000000
#define N_GRAPHS_C 1000

#define LOG2E_F 1.4426950408889634f
#define SALPHA_F 1.7580993408473766f          // scale*alpha
#define SLN2_F   0.7282895255054788f          // scale*ln(2)

// Scratch (no cudaMalloc allowed)
__device__ float d_eon[N_NODES_C];        // segment_sum of edge outputs per receiver
__device__ float d_g[N_GRAPHS_C * 11];    // per-graph accumulators
__device__ float d_EW[96];                // folded edge-stage weights (exp2-space)

__device__ __forceinline__ float ex2(float y) {
    float r;
    asm("ex2.approx.f32 %0, %1;" : "=f"(r) : "f"(y));
    return r;
}

// selu from y = x*log2(e):  selu(x) = s*ln2*max(y,0) + s*a*(2^min(y,0) - 1)
__device__ __forceinline__ float selu_y(float y) {
    float e   = ex2(fminf(y, 0.0f));
    float lin = fmaxf(y, 0.0f);
    return fmaf(SALPHA_F, e, fmaf(SLN2_F, lin, -SALPHA_F));
}

// ---------------------------------------------------------------------------
// Zero scratch (kernel, not memset, so ncu launch indexing is deterministic)
// ---------------------------------------------------------------------------
__global__ void zero_scratch() {
    int i = blockIdx.x * blockDim.x + threadIdx.x;
    int stride = gridDim.x * blockDim.x;
    float4* p = reinterpret_cast<float4*>(d_eon);
    for (int k = i; k < N_NODES_C / 4; k += stride)
        p[k] = make_float4(0.f, 0.f, 0.f, 0.f);
    for (int k = i; k < N_GRAPHS_C * 11; k += stride)
        d_g[k] = 0.f;
}

__global__ void noop_kernel() {}

// ---------------------------------------------------------------------------
// Setup: fold pn_w2 into ue_w1[1:,:] and pre-scale all SELU-arg weights by LOG2E.
// d_EW layout:
//   [0:20)  pn_w1*L       [20:30) pn_b1*L
//   [30:80) M*L (M = pn_w2 @ ue_w1[1:,:])   [80:85) d*L (d = pn_b2 @ ue_w1[1:,:] + ue_b1)
//   [85:90) ue_w1[0,:]*L  [90:95) ue_w2     [95] ue_b2
// ---------------------------------------------------------------------------
__global__ void setup_kernel(const float* __restrict__ pn_w1, const float* __restrict__ pn_b1,
                             const float* __restrict__ pn_w2, const float* __restrict__ pn_b2,
                             const float* __restrict__ ue_w1, const float* __restrict__ ue_b1,
                             const float* __restrict__ ue_w2, const float* __restrict__ ue_b2) {
    int t = threadIdx.x;
    if (t < 20) d_EW[t] = pn_w1[t] * LOG2E_F;
    if (t < 10) d_EW[20 + t] = pn_b1[t] * LOG2E_F;
    if (t < 50) {
        int j = t / 5, k = t % 5;
        float m = 0.0f;
        for (int q = 0; q < 10; ++q)
            m += pn_w2[j * 10 + q] * ue_w1[(1 + q) * 5 + k];
        d_EW[30 + t] = m * LOG2E_F;
    }
    if (t < 5) {
        float dd = ue_b1[t];
        for (int q = 0; q < 10; ++q)
            dd += pn_b2[q] * ue_w1[(1 + q) * 5 + t];
        d_EW[80 + t] = dd * LOG2E_F;
        d_EW[85 + t] = ue_w1[t] * LOG2E_F;   // ue_w1[0][k]
        d_EW[90 + t] = ue_w2[t];
    }
    if (t == 0) d_EW[95] = ue_b2[0];
}

// ---------------------------------------------------------------------------
// Per-edge math (weights register-resident, exp2-space SELU args)
// ---------------------------------------------------------------------------
__device__ __forceinline__ float edge_compute(float nr, float ns, float ev,
                                              const float* __restrict__ W) {
    float c0 = W[80], c1 = W[81], c2 = W[82], c3 = W[83], c4 = W[84];
#pragma unroll
    for (int j = 0; j < 10; ++j) {
        float h = selu_y(fmaf(nr, W[j], fmaf(ns, W[10 + j], W[20 + j])));
        c0 = fmaf(h, W[30 + j * 5 + 0], c0);
        c1 = fmaf(h, W[30 + j * 5 + 1], c1);
        c2 = fmaf(h, W[30 + j * 5 + 2], c2);
        c3 = fmaf(h, W[30 + j * 5 + 3], c3);
        c4 = fmaf(h, W[30 + j * 5 + 4], c4);
    }
#pragma unroll
    for (int it = 0; it < 3; ++it) {
        float acc = W[95];
        acc = fmaf(selu_y(fmaf(ev, W[85], c0)), W[90], acc);
        acc = fmaf(selu_y(fmaf(ev, W[86], c1)), W[91], acc);
        acc = fmaf(selu_y(fmaf(ev, W[87], c2)), W[92], acc);
        acc = fmaf(selu_y(fmaf(ev, W[88], c3)), W[93], acc);
        acc = fmaf(selu_y(fmaf(ev, W[89], c4)), W[94], acc);
        ev = acc;
    }
    return ev;
}

// ---------------------------------------------------------------------------
// Edge stage: 2 edges per iteration, vector index loads, gathers issued early.
// ---------------------------------------------------------------------------
__global__ __launch_bounds__(256) void edge_kernel(
        const float* __restrict__ nodes, const float* __restrict__ edges,
        const int* __restrict__ senders, const int* __restrict__ receivers) {
    float W[96];
#pragma unroll
    for (int i = 0; i < 96; ++i) W[i] = d_EW[i];

    const int2*   r2p = (const int2*)receivers;
    const int2*   s2p = (const int2*)senders;
    const float2* e2p = (const float2*)edges;
    const int NP = N_EDGES_C / 2;

    int stride = gridDim.x * blockDim.x;
    for (int p = blockIdx.x * blockDim.x + threadIdx.x; p < NP; p += stride) {
        int2   rr = r2p[p];
        int2   ss = s2p[p];
        float2 ee = e2p[p];
        // issue all four random gathers up front (MLP=4 on L2 latency)
        float nr0 = __ldg(nodes + rr.x);
        float ns0 = __ldg(nodes + ss.x);
        float nr1 = __ldg(nodes + rr.y);
        float ns1 = __ldg(nodes + ss.y);

        float ev0 = edge_compute(nr0, ns0, ee.x, W);
        atomicAdd(&d_eon[rr.x], ev0);
        float ev1 = edge_compute(nr1, ns1, ee.y, W);
        atomicAdd(&d_eon[rr.y], ev1);
    }
}

// ---------------------------------------------------------------------------
// Node stage: pe MLP + 3 un iterations, warp-aggregated segment sum into d_g.
// ---------------------------------------------------------------------------
__global__ __launch_bounds__(256) void node_kernel(
        const float* __restrict__ nodes, const int* __restrict__ graph_ids,
        const float* __restrict__ pe_w1, const float* __restrict__ pe_b1,
        const float* __restrict__ pe_w2, const float* __restrict__ pe_b2,
        const float* __restrict__ un_w1, const float* __restrict__ un_b1,
        const float* __restrict__ un_w2, const float* __restrict__ un_b2) {
    float PW1[5], PB1[5], PW2[50], PB2[10];
    float UW1[55], UB1[5], UW2[5], UB2v;
#pragma unroll
    for (int i = 0; i < 5; ++i) {
        PW1[i] = __ldg(pe_w1 + i) * LOG2E_F;
        PB1[i] = __ldg(pe_b1 + i) * LOG2E_F;
        UB1[i] = __ldg(un_b1 + i) * LOG2E_F;
        UW2[i] = __ldg(un_w2 + i);
    }
#pragma unroll
    for (int i = 0; i < 50; ++i) PW2[i] = __ldg(pe_w2 + i);
#pragma unroll
    for (int i = 0; i < 10; ++i) PB2[i] = __ldg(pe_b2 + i);
#pragma unroll
    for (int i = 0; i < 55; ++i) UW1[i] = __ldg(un_w1 + i) * LOG2E_F;
    UB2v = __ldg(un_b2);

    int stride = gridDim.x * blockDim.x;
    for (int n = blockIdx.x * blockDim.x + threadIdx.x; n < N_NODES_C; n += stride) {
        float eon = d_eon[n];
        float v[11];
        float hid[5];
#pragma unroll
        for (int k = 0; k < 5; ++k) hid[k] = selu_y(fmaf(eon, PW1[k], PB1[k]));
#pragma unroll
        for (int j = 0; j < 10; ++j) {
            float acc = PB2[j];
#pragma unroll
            for (int k = 0; k < 5; ++k) acc = fmaf(hid[k], PW2[k * 10 + j], acc);
            v[1 + j] = acc;                         // h2_edges[j]
        }
        float c[5];
#pragma unroll
        for (int k = 0; k < 5; ++k) {
            float acc = UB1[k];
#pragma unroll
            for (int t = 0; t < 10; ++t) acc = fmaf(v[1 + t], UW1[(1 + t) * 5 + k], acc);
            c[k] = acc;
        }
        float x = nodes[n];
#pragma unroll
        for (int it = 0; it < 3; ++it) {
            float acc = UB2v;
#pragma unroll
            for (int k = 0; k < 5; ++k)
                acc = fmaf(selu_y(fmaf(x, UW1[k], c[k])), UW2[k], acc);
            x = acc;
        }
        v[0] = x;                                   // h2_nodes

        int gid = graph_ids[n];
        const unsigned mask = 0xffffffffu;
        int g0 = __shfl_sync(mask, gid, 0);
        bool uni = __all_sync(mask, gid == g0);
        if (uni) {
#pragma unroll
            for (int j = 0; j < 11; ++j) {
                float vv = v[j];
#pragma unroll
                for (int off = 16; off > 0; off >>= 1)
                    vv += __shfl_down_sync(mask, vv, off);
                if ((threadIdx.x & 31) == 0) atomicAdd(&d_g[g0 * 11 + j], vv);
            }
        } else {
#pragma unroll
            for (int j = 0; j < 11; ++j)
                atomicAdd(&d_g[gid * 11 + j], v[j]);
        }
    }
}

// ---------------------------------------------------------------------------
// Final: pr MLP + softmax per graph (exp2-space).
// ---------------------------------------------------------------------------
__global__ void graph_kernel(const float* __restrict__ pr_w1, const float* __restrict__ pr_b1,
                             const float* __restrict__ pr_w2, const float* __restrict__ pr_b2,
                             float* __restrict__ out) {
    int g = blockIdx.x * blockDim.x + threadIdx.x;
    if (g >= N_GRAPHS_C) return;
    float gv[11];
#pragma unroll
    for (int i = 0; i < 11; ++i) gv[i] = d_g[g * 11 + i];
    float hid[10];
#pragma unroll
    for (int j = 0; j < 10; ++j) {
        float acc = __ldg(pr_b1 + j) * LOG2E_F;
#pragma unroll
        for (int i = 0; i < 11; ++i)
            acc = fmaf(gv[i], __ldg(pr_w1 + i * 10 + j) * LOG2E_F, acc);
        hid[j] = selu_y(acc);
    }
    // o in exp2-space: softmax(o) == 2^(oy - max)/sum
    float o[10];
    float mx = -1e30f;
#pragma unroll
    for (int k = 0; k < 10; ++k) {
        float acc = __ldg(pr_b2 + k) * LOG2E_F;
#pragma unroll
        for (int j = 0; j < 10; ++j)
            acc = fmaf(hid[j], __ldg(pr_w2 + j * 10 + k) * LOG2E_F, acc);
        o[k] = acc;
        mx = fmaxf(mx, acc);
    }
    float sum = 0.0f;
#pragma unroll
    for (int k = 0; k < 10; ++k) { o[k] = ex2(o[k] - mx); sum += o[k]; }
    float inv = 1.0f / sum;
#pragma unroll
    for (int k = 0; k < 10; ++k) out[g * 10 + k] = o[k] * inv;
}

// ---------------------------------------------------------------------------
extern "C" void kernel_launch(void* const* d_in, const int* in_sizes, int n_in,
                              void* d_out, int out_size) {
    const float* nodes = (const float*)d_in[0];
    const float* edges = (const float*)d_in[1];
    const int *senders, *receivers, *graph_ids;
    const float* w[20];

    if (in_sizes[2] == N_EDGES_C) {
        senders   = (const int*)d_in[2];
        receivers = (const int*)d_in[3];
        graph_ids = (const int*)d_in[4];
        int base = (n_in > 25 && in_sizes[5] == 1) ? 6 : 5;
        for (int i = 0; i < 20; ++i) w[i] = (const float*)d_in[base + i];
    } else {
        for (int i = 0; i < 20; ++i) w[i] = (const float*)d_in[2 + i];
        senders   = (const int*)d_in[22];
        receivers = (const int*)d_in[23];
        graph_ids = (const int*)d_in[24];
    }

    // Launch indices (ncu -s 5 -c 1 profiles index 5 == edge_kernel):
    zero_scratch<<<232, 256>>>();                                   // 0
    setup_kernel<<<1, 64>>>(w[0], w[1], w[2], w[3],
                            w[4], w[5], w[6], w[7]);                // 1
    noop_kernel<<<1, 32>>>();                                       // 2
    noop_kernel<<<1, 32>>>();                                       // 3
    noop_kernel<<<1, 32>>>();                                       // 4
    edge_kernel<<<444, 256>>>(nodes, edges, senders, receivers);    // 5
    node_kernel<<<148, 256>>>(nodes, graph_ids,
                              w[8], w[9], w[10], w[11],
                              w[12], w[13], w[14], w[15]);          // 6
    graph_kernel<<<32, 32>>>(w[16], w[17], w[18], w[19],
                             (float*)d_out);                        // 7
}